// round 1
// baseline (speedup 1.0000x reference)
#include <cuda_runtime.h>

// Problem dims
#define BB 64
#define TT 512
#define DD 128
#define HH 1024
#define BT (BB * TT)

// ---------------- Scan (persistent) config ----------------
#define GM 4            // batch groups
#define GN 32           // column groups
#define MB (BB / GM)    // 16 batches per CTA
#define NB (HH / GN)    // 32 columns per CTA
#define GRID (GM * GN)  // 128 CTAs (<= 148 SMs, 1 CTA/SM -> co-resident)
#define NTHR 256
#define KSPLIT 8
#define KCH (HH / KSPLIT)  // 128
#define HPAD 20            // padded row stride for transposed h (conflict-free, 16B aligned)

#define SCAN_SMEM_FLOATS (HH * NB + HH * HPAD + NTHR * 16)

// ---------------- Projection config ----------------
#define PM 64
#define PN 64
#define APAD 68
#define PROJ_SMEM_FLOATS (DD * APAD + DD * PN)

// Scratch: h double buffer + barrier state (persist across graph replays;
// g_count always returns to 0, g_gen is monotonic and compared by equality).
__device__ __align__(16) float g_h[2][BB * HH];
__device__ unsigned g_count = 0;
__device__ unsigned g_gen = 0;

__device__ __forceinline__ void grid_barrier(unsigned &lg) {
    __threadfence();      // publish this thread's global writes device-wide
    __syncthreads();
    if (threadIdx.x == 0) {
        unsigned target = lg + 1;
        if (atomicAdd(&g_count, 1u) == GRID - 1) {
            atomicExch(&g_count, 0u);
            __threadfence();
            atomicAdd(&g_gen, 1u);
        } else {
            volatile unsigned *gp = &g_gen;
            while ((int)(*gp - target) < 0) { }
        }
        lg = target;
        __threadfence();
    }
    __syncthreads();
}

// =====================================================================
// Persistent scan kernel: 512 sequential steps of
//   z = u_t + h @ W_rec^T ; h = h + (tanh(z) - h) / tau
// W_rec slice lives in SMEM for the whole kernel. h double-buffered in gmem.
// u_t is read from d_out (written by proj kernel) and overwritten with h_t.
// =====================================================================
__global__ void __launch_bounds__(NTHR, 1)
scan_kernel(const float *__restrict__ W_rec, const float *__restrict__ taup,
            float *__restrict__ out) {
    extern __shared__ float smem[];
    float *W_s = smem;                   // [HH][NB]   transposed: W_s[k][n] = W_rec[n0+n][k]
    float *h_s = smem + HH * NB;         // [HH][HPAD] transposed: h_s[k][b] = h_prev[b0+b][k]
    float *red = smem + HH * NB + HH * HPAD;  // [NTHR*16] k-split reduction buffer

    const int tid = threadIdx.x;
    const int cta = blockIdx.x;
    const int gm = cta >> 5;   // 0..3
    const int gn = cta & 31;   // 0..31
    const int b0 = gm * MB;
    const int n0 = gn * NB;
    const float inv_tau = 1.0f / (*taup);

    unsigned lg = 0;
    if (tid == 0) lg = *(volatile unsigned *)&g_gen;  // stable until first barrier

    // ---- One-time: load W_rec slice transposed into SMEM (conflict-free) ----
    {
        const int n = tid & 31;        // lane -> column: STS addresses hit distinct banks
        const int kq = tid >> 5;       // 0..7
        const float *wr = W_rec + (size_t)(n0 + n) * HH;
        for (int it = 0; it < 32; ++it) {
            int c = kq + it * 8;       // 0..255 float4-chunks
            float4 v = *(const float4 *)(wr + c * 4);
            int k = c * 4;
            W_s[(k + 0) * NB + n] = v.x;
            W_s[(k + 1) * NB + n] = v.y;
            W_s[(k + 2) * NB + n] = v.z;
            W_s[(k + 3) * NB + n] = v.w;
        }
    }

    // ---- One-time: zero h0 tile (must be re-zeroed every replay) ----
    for (int i = tid; i < MB * NB; i += NTHR) {
        int bl = i >> 5;   // /NB
        int nl = i & 31;   // %NB
        g_h[0][(size_t)(b0 + bl) * HH + (n0 + nl)] = 0.0f;
    }

    grid_barrier(lg);

    const int ks = tid >> 5;      // k-split id 0..7
    const int sp = tid & 31;      // spatial micro-tile id
    const int sb = sp & 3;        // *4 -> batch offset
    const int sn = sp >> 2;       // *4 -> column offset
    const int ldb = tid & 15;     // h-load: lane -> batch (conflict-free transpose STS)
    const int ldk = tid >> 4;     // h-load: 0..15 k-group

    for (int t = 0; t < TT; ++t) {
        const int cur = t & 1;
        const int nxt = cur ^ 1;

        // ---- Load h slice [MB][HH] transposed into h_s (L2, bypass L1) ----
        {
            const float *hrow = g_h[cur] + (size_t)(b0 + ldb) * HH;
            #pragma unroll
            for (int it = 0; it < 16; ++it) {
                int c = ldk + it * 16;  // 0..255
                float4 v = __ldcg((const float4 *)(hrow + c * 4));
                int k = c * 4;
                h_s[(k + 0) * HPAD + ldb] = v.x;
                h_s[(k + 1) * HPAD + ldb] = v.y;
                h_s[(k + 2) * HPAD + ldb] = v.z;
                h_s[(k + 3) * HPAD + ldb] = v.w;
            }
        }
        __syncthreads();

        // ---- Main GEMM: 4x4 micro-tile per thread over K-chunk of 128 ----
        float acc[4][4];
        #pragma unroll
        for (int i = 0; i < 4; ++i)
            #pragma unroll
            for (int j = 0; j < 4; ++j) acc[i][j] = 0.0f;

        const float *hp = h_s + ks * KCH * HPAD + sb * 4;
        const float *wp = W_s + ks * KCH * NB + sn * 4;
        #pragma unroll 8
        for (int k = 0; k < KCH; ++k) {
            float4 hv = *(const float4 *)(hp + k * HPAD);
            float4 wv = *(const float4 *)(wp + k * NB);
            acc[0][0] += hv.x * wv.x; acc[0][1] += hv.x * wv.y;
            acc[0][2] += hv.x * wv.z; acc[0][3] += hv.x * wv.w;
            acc[1][0] += hv.y * wv.x; acc[1][1] += hv.y * wv.y;
            acc[1][2] += hv.y * wv.z; acc[1][3] += hv.y * wv.w;
            acc[2][0] += hv.z * wv.x; acc[2][1] += hv.z * wv.y;
            acc[2][2] += hv.z * wv.z; acc[2][3] += hv.z * wv.w;
            acc[3][0] += hv.w * wv.x; acc[3][1] += hv.w * wv.y;
            acc[3][2] += hv.w * wv.z; acc[3][3] += hv.w * wv.w;
        }

        // ---- k-split reduction ----
        #pragma unroll
        for (int i = 0; i < 4; ++i)
            #pragma unroll
            for (int j = 0; j < 4; ++j) red[tid * 16 + i * 4 + j] = acc[i][j];
        __syncthreads();

        // ---- Epilogue: z = u + s ; h' = h + (tanh(z)-h)/tau ----
        for (int o = tid; o < MB * NB; o += NTHR) {
            int spatial = o >> 4;
            int m = o & 15;
            float s = 0.0f;
            #pragma unroll
            for (int q = 0; q < KSPLIT; ++q)
                s += red[((q << 5) + spatial) * 16 + m];
            int i = m >> 2, j = m & 3;
            int bl = (spatial & 3) * 4 + i;
            int nl = (spatial >> 2) * 4 + j;
            int bg = b0 + bl;
            int ng = n0 + nl;
            size_t oidx = ((size_t)bg * TT + t) * HH + ng;
            float u = out[oidx];
            float hprev = h_s[ng * HPAD + bl];  // h_prev[bg][ng] from transposed smem
            float f = tanhf(u + s);
            float hn = hprev + (f - hprev) * inv_tau;
            out[oidx] = hn;
            g_h[nxt][(size_t)bg * HH + ng] = hn;
            if (t == TT - 1)
                out[(size_t)BB * TT * HH + (size_t)bg * HH + ng] = hn;  // h_last
        }

        if (t < TT - 1) grid_barrier(lg);
    }
}

// =====================================================================
// Projection kernel: u[bt][h] = seq[bt]·W_in[h] + b_in[h] + bias[h]
// written directly into d_out's out_seq region.
// =====================================================================
__global__ void __launch_bounds__(256, 2)
proj_kernel(const float *__restrict__ seq, const float *__restrict__ W_in,
            const float *__restrict__ b_in, const float *__restrict__ bias,
            float *__restrict__ out) {
    extern __shared__ float sm[];
    float *A_s = sm;             // [DD][APAD]  A_s[d][m] = seq[bt0+m][d]
    float *B_s = sm + DD * APAD; // [DD][PN]    B_s[d][n] = W_in[h0+n][d]

    const int tid = threadIdx.x;
    const int bt0 = blockIdx.x * PM;
    const int h0 = blockIdx.y * PN;

    // transpose-load tiles (lane -> row: conflict-free STS)
    {
        const int m = tid & 63;
        const int kg = tid >> 6;  // 0..3
        const float *arow = seq + (size_t)(bt0 + m) * DD;
        const float *brow = W_in + (size_t)(h0 + m) * DD;
        #pragma unroll
        for (int it = 0; it < 8; ++it) {
            int c = kg + it * 4;  // 0..31
            float4 a = *(const float4 *)(arow + c * 4);
            float4 w = *(const float4 *)(brow + c * 4);
            int k = c * 4;
            A_s[(k + 0) * APAD + m] = a.x; A_s[(k + 1) * APAD + m] = a.y;
            A_s[(k + 2) * APAD + m] = a.z; A_s[(k + 3) * APAD + m] = a.w;
            B_s[(k + 0) * PN + m] = w.x; B_s[(k + 1) * PN + m] = w.y;
            B_s[(k + 2) * PN + m] = w.z; B_s[(k + 3) * PN + m] = w.w;
        }
    }
    __syncthreads();

    const int smi = tid & 15;  // row micro-tile
    const int sn = tid >> 4;   // col micro-tile (0..15)
    float acc[4][4];
    #pragma unroll
    for (int i = 0; i < 4; ++i)
        #pragma unroll
        for (int j = 0; j < 4; ++j) acc[i][j] = 0.0f;

    const float *ap = A_s + smi * 4;
    const float *bp = B_s + sn * 4;
    #pragma unroll 8
    for (int k = 0; k < DD; ++k) {
        float4 av = *(const float4 *)(ap + k * APAD);
        float4 bv = *(const float4 *)(bp + k * PN);
        acc[0][0] += av.x * bv.x; acc[0][1] += av.x * bv.y;
        acc[0][2] += av.x * bv.z; acc[0][3] += av.x * bv.w;
        acc[1][0] += av.y * bv.x; acc[1][1] += av.y * bv.y;
        acc[1][2] += av.y * bv.z; acc[1][3] += av.y * bv.w;
        acc[2][0] += av.z * bv.x; acc[2][1] += av.z * bv.y;
        acc[2][2] += av.z * bv.z; acc[2][3] += av.z * bv.w;
        acc[3][0] += av.w * bv.x; acc[3][1] += av.w * bv.y;
        acc[3][2] += av.w * bv.z; acc[3][3] += av.w * bv.w;
    }

    float bb[4];
    #pragma unroll
    for (int j = 0; j < 4; ++j)
        bb[j] = b_in[h0 + sn * 4 + j] + bias[h0 + sn * 4 + j];

    #pragma unroll
    for (int i = 0; i < 4; ++i) {
        int bt = bt0 + smi * 4 + i;
        float4 o;
        o.x = acc[i][0] + bb[0];
        o.y = acc[i][1] + bb[1];
        o.z = acc[i][2] + bb[2];
        o.w = acc[i][3] + bb[3];
        *(float4 *)(out + (size_t)bt * HH + h0 + sn * 4) = o;
    }
}

extern "C" void kernel_launch(void *const *d_in, const int *in_sizes, int n_in,
                              void *d_out, int out_size) {
    const float *seq = (const float *)d_in[0];
    const float *W_in = (const float *)d_in[1];
    const float *b_in = (const float *)d_in[2];
    const float *W_rec = (const float *)d_in[3];
    const float *bias = (const float *)d_in[4];
    const float *tau = (const float *)d_in[5];
    float *out = (float *)d_out;

    cudaFuncSetAttribute(proj_kernel, cudaFuncAttributeMaxDynamicSharedMemorySize,
                         PROJ_SMEM_FLOATS * (int)sizeof(float));
    cudaFuncSetAttribute(scan_kernel, cudaFuncAttributeMaxDynamicSharedMemorySize,
                         SCAN_SMEM_FLOATS * (int)sizeof(float));

    proj_kernel<<<dim3(BT / PM, HH / PN), 256, PROJ_SMEM_FLOATS * sizeof(float)>>>(
        seq, W_in, b_in, bias, out);
    scan_kernel<<<GRID, NTHR, SCAN_SMEM_FLOATS * sizeof(float)>>>(W_rec, tau, out);
}

// round 8
// speedup vs baseline: 1.9242x; 1.9242x over previous
#include <cuda_runtime.h>
#include <cuda_bf16.h>
#include <cstdint>

// Problem dims
#define BB 64
#define TT 512
#define HH 1024
#define DD 128
#define BT (BB * TT)

// ---------------- Scan config ----------------
#define GRID 128        // 4 batch-groups x 32 col-groups, 1 CTA/SM co-resident
#define NTHR 512        // 16 warps: warp w -> (kchunk w>>1, col-half w&1)
#define MB 16
#define NB 32

#define PITCH_H 2064    // bytes per staged h row (1024 bf16 + 8 pad)
#define OFF_H1 0
#define OFF_H2 33024
#define OFF_ZR 66048
#define ZP 36           // zred row pitch (floats)
#define OFF_HS 84480
#define SMEM_TOTAL 86528

// ---------------- Projection config ----------------
#define PM 64
#define PN 64
#define APAD 68
#define PROJ_SMEM_FLOATS (DD * APAD + DD * PN)

// Scratch (persists across graph replays; re-initialized deterministically)
__device__ __align__(16) __nv_bfloat16 g_hs[2][2][BB][HH];  // [buf][split][b][k]
__device__ unsigned g_count = 0;
__device__ unsigned g_gen = 0;

// ======================= helpers =======================
__device__ __forceinline__ void mma16816(float *d, const uint32_t *a, const uint32_t *b) {
    asm volatile(
        "mma.sync.aligned.m16n8k16.row.col.f32.bf16.bf16.f32 "
        "{%0,%1,%2,%3}, {%4,%5,%6,%7}, {%8,%9}, {%0,%1,%2,%3};"
        : "+f"(d[0]), "+f"(d[1]), "+f"(d[2]), "+f"(d[3])
        : "r"(a[0]), "r"(a[1]), "r"(a[2]), "r"(a[3]), "r"(b[0]), "r"(b[1]));
}

__device__ __forceinline__ void ldsm_x4(uint32_t *r, uint32_t addr) {
    asm volatile("ldmatrix.sync.aligned.m8n8.x4.shared.b16 {%0,%1,%2,%3}, [%4];"
        : "=r"(r[0]), "=r"(r[1]), "=r"(r[2]), "=r"(r[3]) : "r"(addr));
}

// Split fp32 pair -> (primary bf16x2, residual bf16x2), intrinsics only.
__device__ __forceinline__ void split2(float x, float y, uint32_t &p, uint32_t &r) {
    __nv_bfloat16 px = __float2bfloat16(x), py = __float2bfloat16(y);
    __nv_bfloat16 rx = __float2bfloat16(x - __bfloat162float(px));
    __nv_bfloat16 ry = __float2bfloat16(y - __bfloat162float(py));
    p = (uint32_t)__bfloat16_as_ushort(px) | ((uint32_t)__bfloat16_as_ushort(py) << 16);
    r = (uint32_t)__bfloat16_as_ushort(rx) | ((uint32_t)__bfloat16_as_ushort(ry) << 16);
}

__device__ __forceinline__ void grid_barrier(unsigned &lg) {
    __threadfence();
    __syncthreads();
    if (threadIdx.x == 0) {
        unsigned target = lg + 1;
        if (atomicAdd(&g_count, 1u) == GRID - 1) {
            atomicExch(&g_count, 0u);
            __threadfence();
            atomicAdd(&g_gen, 1u);
        } else {
            volatile unsigned *gp = &g_gen;
            unsigned c = 0;
            while ((int)(*gp - target) < 0) {
                if (++c > (1u << 26)) break;   // safety valve, never hit when healthy
            }
        }
        lg = target;
        __threadfence();
    }
    __syncthreads();
}

// =====================================================================
// Persistent HMMA scan: z[b][n] = u_t[b][n] + sum_k h[b][k] W[n][k]
// 16 warps: warp (kw, nh) owns K-chunk kw*128 and 16-col half nh.
// W bf16-split fragments in REGISTERS (64 u32/thread, loaded once).
// h bf16-split staged to SMEM each step; 3-term split product, f32 acc.
// =====================================================================
__global__ void __launch_bounds__(NTHR, 1)
scan_mma(const float *__restrict__ W_rec, const float *__restrict__ taup,
         float *__restrict__ out) {
    extern __shared__ char smem[];
    const uint32_t sb = (uint32_t)__cvta_generic_to_shared(smem);
    const int tid = threadIdx.x;
    const int wid = tid >> 5;
    const int lane = tid & 31;
    const int cta = blockIdx.x;
    const int gm = cta >> 5;        // 0..3
    const int gn = cta & 31;        // 0..31
    const int b0 = gm * MB;
    const int n0 = gn * NB;
    const float inv_tau = 1.0f / (*taup);

    const int nh = wid & 1;         // column half -> cols nh*16..+16
    const int kw = wid >> 1;        // K-chunk id (0..7)
    const int kc = kw * 128;
    const int lq = lane >> 2;       // 0..7
    const int lr = lane & 3;        // 0..3

    // ---- One-time: W slice fragments -> registers (bf16 split pair) ----
    uint32_t Wr1[8][2][2], Wr2[8][2][2];
    #pragma unroll
    for (int ks = 0; ks < 8; ++ks) {
        #pragma unroll
        for (int nt = 0; nt < 2; ++nt) {
            const float *wrow = W_rec + (size_t)(n0 + nh * 16 + nt * 8 + lq) * HH
                                + kc + ks * 16 + 2 * lr;
            split2(wrow[0], wrow[1], Wr1[ks][nt][0], Wr2[ks][nt][0]);
            split2(wrow[8], wrow[9], Wr1[ks][nt][1], Wr2[ks][nt][1]);
        }
    }

    // ---- One-time: zero fp32 h slice (smem) and bf16 split buf0 (gmem) ----
    float *hs = (float *)(smem + OFF_HS);
    {
        int b = tid >> 5, n = tid & 31;       // tid covers all 512 outputs
        hs[tid] = 0.0f;
        __nv_bfloat16 z = __float2bfloat16(0.0f);
        g_hs[0][0][b0 + b][n0 + n] = z;
        g_hs[0][1][b0 + b][n0 + n] = z;
    }

    unsigned lg = 0;
    if (tid == 0) lg = *(volatile unsigned *)&g_gen;
    __syncthreads();
    grid_barrier(lg);

    float *zr = (float *)(smem + OFF_ZR);
    // ldmatrix lane address base (A fragments of warp's k-chunk)
    const uint32_t ab1 = sb + OFF_H1 +
        (uint32_t)((lane & 15) * PITCH_H + (lane >> 4) * 16 + kc * 2);
    const uint32_t ab2 = ab1 + (OFF_H2 - OFF_H1);

    const int ob = tid >> 5, on = tid & 31;     // epilogue output (1/thread)

    for (int t = 0; t < TT; ++t) {
        const int rb = t & 1;
        const int nb = rb ^ 1;

        // ---- Stage h slice [2 splits][16 b][1024 k] bf16 -> smem ----
        #pragma unroll
        for (int i = 0; i < 8; ++i) {
            int id = i * NTHR + tid;            // 0..4095 uint4s
            int row = id >> 7;                  // 0..31 : split = row>>4, b = row&15
            int c16 = id & 127;
            const uint4 *src = (const uint4 *)&g_hs[rb][row >> 4][b0 + (row & 15)][c16 * 8];
            uint4 v = __ldcg(src);
            *(uint4 *)(smem + (row >> 4 ? OFF_H2 : OFF_H1)
                       + (row & 15) * PITCH_H + c16 * 16) = v;
        }
        __syncthreads();

        // ---- HMMA: 8 k-steps x 2 n-tiles x 3 split terms ----
        float D[2][4];
        #pragma unroll
        for (int nt = 0; nt < 2; ++nt)
            #pragma unroll
            for (int j = 0; j < 4; ++j) D[nt][j] = 0.0f;

        #pragma unroll
        for (int ks = 0; ks < 8; ++ks) {
            uint32_t a1[4], a2[4];
            ldsm_x4(a1, ab1 + ks * 32);
            ldsm_x4(a2, ab2 + ks * 32);
            #pragma unroll
            for (int nt = 0; nt < 2; ++nt) {
                mma16816(D[nt], a1, Wr1[ks][nt]);
                mma16816(D[nt], a1, Wr2[ks][nt]);
                mma16816(D[nt], a2, Wr1[ks][nt]);
            }
        }

        // ---- k-split partials -> smem zred[8][16][ZP] ----
        {
            int base = kw * (16 * ZP) + lq * ZP + nh * 16 + 2 * lr;
            #pragma unroll
            for (int nt = 0; nt < 2; ++nt) {
                zr[base + nt * 8]     = D[nt][0];
                zr[base + nt * 8 + 1] = D[nt][1];
                zr[base + 8 * ZP + nt * 8]     = D[nt][2];
                zr[base + 8 * ZP + nt * 8 + 1] = D[nt][3];
            }
        }
        __syncthreads();

        // ---- Epilogue: sum 8 partials; h' = h + (tanh(u+z)-h)/tau ----
        {
            float s = 0.0f;
            #pragma unroll
            for (int q = 0; q < 8; ++q) s += zr[q * (16 * ZP) + ob * ZP + on];
            int bg = b0 + ob, ng = n0 + on;
            size_t oidx = ((size_t)bg * TT + t) * HH + ng;
            float u = out[oidx];
            float hp = hs[tid];
            float f = tanhf(u + s);
            float hn = hp + (f - hp) * inv_tau;
            out[oidx] = hn;
            hs[tid] = hn;
            __nv_bfloat16 h1 = __float2bfloat16(hn);
            __nv_bfloat16 h2 = __float2bfloat16(hn - __bfloat162float(h1));
            g_hs[nb][0][bg][ng] = h1;
            g_hs[nb][1][bg][ng] = h2;
            if (t == TT - 1)
                out[(size_t)BB * TT * HH + (size_t)bg * HH + ng] = hn;
        }

        if (t < TT - 1) grid_barrier(lg);
    }
}

// =====================================================================
// Projection kernel: u[bt][h] = seq[bt]·W_in[h] + b_in[h] + bias[h]
// =====================================================================
__global__ void __launch_bounds__(256, 2)
proj_kernel(const float *__restrict__ seq, const float *__restrict__ W_in,
            const float *__restrict__ b_in, const float *__restrict__ bias,
            float *__restrict__ out) {
    extern __shared__ char smemp[];
    float *A_s = (float *)smemp;
    float *B_s = (float *)smemp + DD * APAD;

    const int tid = threadIdx.x;
    const int bt0 = blockIdx.x * PM;
    const int h0 = blockIdx.y * PN;

    {
        const int m = tid & 63;
        const int kg = tid >> 6;
        const float *arow = seq + (size_t)(bt0 + m) * DD;
        const float *brow = W_in + (size_t)(h0 + m) * DD;
        #pragma unroll
        for (int it = 0; it < 8; ++it) {
            int c = kg + it * 4;
            float4 a = *(const float4 *)(arow + c * 4);
            float4 w = *(const float4 *)(brow + c * 4);
            int k = c * 4;
            A_s[(k + 0) * APAD + m] = a.x; A_s[(k + 1) * APAD + m] = a.y;
            A_s[(k + 2) * APAD + m] = a.z; A_s[(k + 3) * APAD + m] = a.w;
            B_s[(k + 0) * PN + m] = w.x; B_s[(k + 1) * PN + m] = w.y;
            B_s[(k + 2) * PN + m] = w.z; B_s[(k + 3) * PN + m] = w.w;
        }
    }
    __syncthreads();

    const int smi = tid & 15;
    const int sn = tid >> 4;
    float acc[4][4];
    #pragma unroll
    for (int i = 0; i < 4; ++i)
        #pragma unroll
        for (int j = 0; j < 4; ++j) acc[i][j] = 0.0f;

    const float *ap = A_s + smi * 4;
    const float *bp = B_s + sn * 4;
    #pragma unroll 8
    for (int k = 0; k < DD; ++k) {
        float4 av = *(const float4 *)(ap + k * APAD);
        float4 bv = *(const float4 *)(bp + k * PN);
        acc[0][0] += av.x * bv.x; acc[0][1] += av.x * bv.y;
        acc[0][2] += av.x * bv.z; acc[0][3] += av.x * bv.w;
        acc[1][0] += av.y * bv.x; acc[1][1] += av.y * bv.y;
        acc[1][2] += av.y * bv.z; acc[1][3] += av.y * bv.w;
        acc[2][0] += av.z * bv.x; acc[2][1] += av.z * bv.y;
        acc[2][2] += av.z * bv.z; acc[2][3] += av.z * bv.w;
        acc[3][0] += av.w * bv.x; acc[3][1] += av.w * bv.y;
        acc[3][2] += av.w * bv.z; acc[3][3] += av.w * bv.w;
    }

    float bb[4];
    #pragma unroll
    for (int j = 0; j < 4; ++j)
        bb[j] = b_in[h0 + sn * 4 + j] + bias[h0 + sn * 4 + j];

    #pragma unroll
    for (int i = 0; i < 4; ++i) {
        int bt = bt0 + smi * 4 + i;
        float4 o;
        o.x = acc[i][0] + bb[0];
        o.y = acc[i][1] + bb[1];
        o.z = acc[i][2] + bb[2];
        o.w = acc[i][3] + bb[3];
        *(float4 *)(out + (size_t)bt * HH + h0 + sn * 4) = o;
    }
}

extern "C" void kernel_launch(void *const *d_in, const int *in_sizes, int n_in,
                              void *d_out, int out_size) {
    const float *seq = (const float *)d_in[0];
    const float *W_in = (const float *)d_in[1];
    const float *b_in = (const float *)d_in[2];
    const float *W_rec = (const float *)d_in[3];
    const float *bias = (const float *)d_in[4];
    const float *tau = (const float *)d_in[5];
    float *out = (float *)d_out;

    cudaFuncSetAttribute(proj_kernel, cudaFuncAttributeMaxDynamicSharedMemorySize,
                         PROJ_SMEM_FLOATS * (int)sizeof(float));
    cudaFuncSetAttribute(scan_mma, cudaFuncAttributeMaxDynamicSharedMemorySize,
                         SMEM_TOTAL);

    proj_kernel<<<dim3(BT / PM, HH / PN), 256, PROJ_SMEM_FLOATS * sizeof(float)>>>(
        seq, W_in, b_in, bias, out);
    scan_mma<<<GRID, NTHR, SMEM_TOTAL>>>(W_rec, tau, out);
}

// round 10
// speedup vs baseline: 2.3263x; 1.2090x over previous
#include <cuda_runtime.h>
#include <cuda_bf16.h>
#include <cstdint>

// Problem dims
#define BB 64
#define TT 512
#define HH 1024
#define DD 128
#define BT (BB * TT)

// ---------------- Scan config ----------------
#define GRID 128        // 4 batch-groups x 32 col-groups, 1 CTA/SM co-resident
#define NTHR 512        // 16 warps: warp w -> (kchunk w>>1, col-half w&1)
#define MB 16
#define NB 32

#define PITCH_H 2064    // bytes per staged h row (1024 bf16 + 8 pad)
#define OFF_H1 0
#define OFF_H2 33024
#define OFF_ZR 66048
#define ZP 36           // zred row pitch (floats)
#define OFF_HS 84480
#define SMEM_TOTAL 86528

// ---------------- Projection config ----------------
#define PM 64
#define PN 64
#define APAD 68
#define PROJ_SMEM_FLOATS (DD * APAD + DD * PN)

// Scratch (persists across graph replays; deterministic per replay)
__device__ __align__(16) __nv_bfloat16 g_hs[2][2][BB][HH];  // [buf][split][b][k]
// Per-CTA progress flags, one 128B line each. Monotonic; +TT per replay (uniform).
__device__ unsigned g_flags[4][32][32];

// ======================= helpers =======================
__device__ __forceinline__ void mma16816(float *d, const uint32_t *a, const uint32_t *b) {
    asm volatile(
        "mma.sync.aligned.m16n8k16.row.col.f32.bf16.bf16.f32 "
        "{%0,%1,%2,%3}, {%4,%5,%6,%7}, {%8,%9}, {%0,%1,%2,%3};"
        : "+f"(d[0]), "+f"(d[1]), "+f"(d[2]), "+f"(d[3])
        : "r"(a[0]), "r"(a[1]), "r"(a[2]), "r"(a[3]), "r"(b[0]), "r"(b[1]));
}

__device__ __forceinline__ void ldsm_x4(uint32_t *r, uint32_t addr) {
    asm volatile("ldmatrix.sync.aligned.m8n8.x4.shared.b16 {%0,%1,%2,%3}, [%4];"
        : "=r"(r[0]), "=r"(r[1]), "=r"(r[2]), "=r"(r[3]) : "r"(addr));
}

// Split fp32 pair -> (primary bf16x2, residual bf16x2)
__device__ __forceinline__ void split2(float x, float y, uint32_t &p, uint32_t &r) {
    __nv_bfloat16 px = __float2bfloat16(x), py = __float2bfloat16(y);
    __nv_bfloat16 rx = __float2bfloat16(x - __bfloat162float(px));
    __nv_bfloat16 ry = __float2bfloat16(y - __bfloat162float(py));
    p = (uint32_t)__bfloat16_as_ushort(px) | ((uint32_t)__bfloat16_as_ushort(py) << 16);
    r = (uint32_t)__bfloat16_as_ushort(rx) | ((uint32_t)__bfloat16_as_ushort(ry) << 16);
}

// =====================================================================
// Persistent HMMA scan: z[b][n] = u_t[b][n] + sum_k h[b][k] W[n][k]
// Group-local flag barrier: CTA (gm,gn) only depends on the 32 CTAs
// sharing gm. Publisher: fence + sync + atomicExch(own flag).
// Waiter: 32 lanes of warp0 poll the 32 group flags in parallel.
// ALL spins bounded: a broken sync drains fast and fails correctness
// instead of wedging the container.
// =====================================================================
__global__ void __launch_bounds__(NTHR, 1)
scan_mma(const float *__restrict__ W_rec, const float *__restrict__ taup,
         float *__restrict__ out) {
    extern __shared__ char smem[];
    const uint32_t sb = (uint32_t)__cvta_generic_to_shared(smem);
    const int tid = threadIdx.x;
    const int wid = tid >> 5;
    const int lane = tid & 31;
    const int cta = blockIdx.x;
    const int gm = cta >> 5;        // 0..3
    const int gn = cta & 31;        // 0..31
    const int b0 = gm * MB;
    const int n0 = gn * NB;
    const float inv_tau = 1.0f / (*taup);

    const int nh = wid & 1;         // column half -> cols nh*16..+16
    const int kw = wid >> 1;        // K-chunk id (0..7)
    const int kc = kw * 128;
    const int lq = lane >> 2;       // 0..7
    const int lr = lane & 3;        // 0..3

    // Flag base: own flag (this CTA is its only writer; all CTAs' flags are
    // equal at entry since every launch publishes exactly TT increments).
    const unsigned base = *(volatile unsigned *)&g_flags[gm][gn][0];

    // ---- One-time: W slice fragments -> registers (bf16 split pair) ----
    uint32_t Wr1[8][2][2], Wr2[8][2][2];
    #pragma unroll
    for (int ks = 0; ks < 8; ++ks) {
        #pragma unroll
        for (int nt = 0; nt < 2; ++nt) {
            const float *wrow = W_rec + (size_t)(n0 + nh * 16 + nt * 8 + lq) * HH
                                + kc + ks * 16 + 2 * lr;
            split2(wrow[0], wrow[1], Wr1[ks][nt][0], Wr2[ks][nt][0]);
            split2(wrow[8], wrow[9], Wr1[ks][nt][1], Wr2[ks][nt][1]);
        }
    }

    // ---- One-time: zero fp32 h slice (smem) and bf16 split buf0 (gmem) ----
    float *hs = (float *)(smem + OFF_HS);
    const int ob = tid >> 5, on = tid & 31;     // this thread's output element
    hs[tid] = 0.0f;
    {
        __nv_bfloat16 z = __float2bfloat16(0.0f);
        g_hs[0][0][b0 + ob][n0 + on] = z;
        g_hs[0][1][b0 + ob][n0 + on] = z;
    }

    // publish "init done" = base + 1
    __threadfence();
    __syncthreads();
    if (tid == 0) atomicExch(&g_flags[gm][gn][0], base + 1u);

    float *zr = (float *)(smem + OFF_ZR);
    const uint32_t ab1 = sb + OFF_H1 +
        (uint32_t)((lane & 15) * PITCH_H + (lane >> 4) * 16 + kc * 2);
    const uint32_t ab2 = ab1 + (OFF_H2 - OFF_H1);

    const int bg = b0 + ob, ng = n0 + on;
    size_t oidx = (size_t)bg * TT * HH + ng;          // advances by HH per step
    volatile unsigned *myflag_row = &g_flags[gm][0][0];

    for (int t = 0; t < TT; ++t) {
        const int rb = t & 1;
        const int nb = rb ^ 1;

        // ---- Wait: all 32 group flags >= base + t + 1 (parallel, BOUNDED) ----
        if (wid == 0) {
            const unsigned target = base + (unsigned)t + 1u;
            volatile unsigned *fp = myflag_row + lane * 32;
            unsigned c = 0;
            while ((int)(*fp - target) < 0) {
                if (++c > (1u << 26)) break;          // fail-fast, never hit healthy
                if (c > 4096u) __nanosleep(64);       // backoff after warm spin
            }
        }
        __syncthreads();
        __threadfence();   // acquire side: order subsequent loads after poll

        // ---- Prefetch u_t (hides DRAM latency behind staging + MMA) ----
        float u = __ldcg(out + oidx);

        // ---- Stage h slice [2 splits][16 b][1024 k] bf16 -> smem ----
        #pragma unroll
        for (int i = 0; i < 8; ++i) {
            int id = i * NTHR + tid;            // 0..4095 uint4s
            int row = id >> 7;                  // split = row>>4, b = row&15
            int c16 = id & 127;
            const uint4 *src = (const uint4 *)&g_hs[rb][row >> 4][b0 + (row & 15)][c16 * 8];
            uint4 v = __ldcg(src);
            *(uint4 *)(smem + (row >> 4 ? OFF_H2 : OFF_H1)
                       + (row & 15) * PITCH_H + c16 * 16) = v;
        }
        __syncthreads();

        // ---- HMMA: 8 k-steps x 2 n-tiles x 3 split terms ----
        float D[2][4];
        #pragma unroll
        for (int nt = 0; nt < 2; ++nt)
            #pragma unroll
            for (int j = 0; j < 4; ++j) D[nt][j] = 0.0f;

        #pragma unroll
        for (int ks = 0; ks < 8; ++ks) {
            uint32_t a1[4], a2[4];
            ldsm_x4(a1, ab1 + ks * 32);
            ldsm_x4(a2, ab2 + ks * 32);
            #pragma unroll
            for (int nt = 0; nt < 2; ++nt) {
                mma16816(D[nt], a1, Wr1[ks][nt]);
                mma16816(D[nt], a1, Wr2[ks][nt]);
                mma16816(D[nt], a2, Wr1[ks][nt]);
            }
        }

        // ---- k-split partials -> smem zred[8][16][ZP] ----
        {
            int zb = kw * (16 * ZP) + lq * ZP + nh * 16 + 2 * lr;
            #pragma unroll
            for (int nt = 0; nt < 2; ++nt) {
                zr[zb + nt * 8]     = D[nt][0];
                zr[zb + nt * 8 + 1] = D[nt][1];
                zr[zb + 8 * ZP + nt * 8]     = D[nt][2];
                zr[zb + 8 * ZP + nt * 8 + 1] = D[nt][3];
            }
        }
        __syncthreads();

        // ---- Epilogue: sum 8 partials; h' = h + (tanh(u+z)-h)/tau ----
        {
            float s = 0.0f;
            #pragma unroll
            for (int q = 0; q < 8; ++q) s += zr[q * (16 * ZP) + ob * ZP + on];
            float hp = hs[tid];
            float f = tanhf(u + s);
            float hn = hp + (f - hp) * inv_tau;
            out[oidx] = hn;
            hs[tid] = hn;
            __nv_bfloat16 h1 = __float2bfloat16(hn);
            __nv_bfloat16 h2 = __float2bfloat16(hn - __bfloat162float(h1));
            g_hs[nb][0][bg][ng] = h1;
            g_hs[nb][1][bg][ng] = h2;
            if (t == TT - 1)
                out[(size_t)BB * TT * HH + (size_t)bg * HH + ng] = hn;
        }
        oidx += HH;

        // ---- Publish step completion (skip after last step) ----
        if (t < TT - 1) {
            __threadfence();
            __syncthreads();
            if (tid == 0) atomicExch(&g_flags[gm][gn][0], base + (unsigned)t + 2u);
        }
    }
}

// =====================================================================
// Projection kernel: u[bt][h] = seq[bt]·W_in[h] + b_in[h] + bias[h]
// =====================================================================
__global__ void __launch_bounds__(256, 2)
proj_kernel(const float *__restrict__ seq, const float *__restrict__ W_in,
            const float *__restrict__ b_in, const float *__restrict__ bias,
            float *__restrict__ out) {
    extern __shared__ char smemp[];
    float *A_s = (float *)smemp;
    float *B_s = (float *)smemp + DD * APAD;

    const int tid = threadIdx.x;
    const int bt0 = blockIdx.x * PM;
    const int h0 = blockIdx.y * PN;

    {
        const int m = tid & 63;
        const int kg = tid >> 6;
        const float *arow = seq + (size_t)(bt0 + m) * DD;
        const float *brow = W_in + (size_t)(h0 + m) * DD;
        #pragma unroll
        for (int it = 0; it < 8; ++it) {
            int c = kg + it * 4;
            float4 a = *(const float4 *)(arow + c * 4);
            float4 w = *(const float4 *)(brow + c * 4);
            int k = c * 4;
            A_s[(k + 0) * APAD + m] = a.x; A_s[(k + 1) * APAD + m] = a.y;
            A_s[(k + 2) * APAD + m] = a.z; A_s[(k + 3) * APAD + m] = a.w;
            B_s[(k + 0) * PN + m] = w.x; B_s[(k + 1) * PN + m] = w.y;
            B_s[(k + 2) * PN + m] = w.z; B_s[(k + 3) * PN + m] = w.w;
        }
    }
    __syncthreads();

    const int smi = tid & 15;
    const int sn = tid >> 4;
    float acc[4][4];
    #pragma unroll
    for (int i = 0; i < 4; ++i)
        #pragma unroll
        for (int j = 0; j < 4; ++j) acc[i][j] = 0.0f;

    const float *ap = A_s + smi * 4;
    const float *bp = B_s + sn * 4;
    #pragma unroll 8
    for (int k = 0; k < DD; ++k) {
        float4 av = *(const float4 *)(ap + k * APAD);
        float4 bv = *(const float4 *)(bp + k * PN);
        acc[0][0] += av.x * bv.x; acc[0][1] += av.x * bv.y;
        acc[0][2] += av.x * bv.z; acc[0][3] += av.x * bv.w;
        acc[1][0] += av.y * bv.x; acc[1][1] += av.y * bv.y;
        acc[1][2] += av.y * bv.z; acc[1][3] += av.y * bv.w;
        acc[2][0] += av.z * bv.x; acc[2][1] += av.z * bv.y;
        acc[2][2] += av.z * bv.z; acc[2][3] += av.z * bv.w;
        acc[3][0] += av.w * bv.x; acc[3][1] += av.w * bv.y;
        acc[3][2] += av.w * bv.z; acc[3][3] += av.w * bv.w;
    }

    float bb[4];
    #pragma unroll
    for (int j = 0; j < 4; ++j)
        bb[j] = b_in[h0 + sn * 4 + j] + bias[h0 + sn * 4 + j];

    #pragma unroll
    for (int i = 0; i < 4; ++i) {
        int bt = bt0 + smi * 4 + i;
        float4 o;
        o.x = acc[i][0] + bb[0];
        o.y = acc[i][1] + bb[1];
        o.z = acc[i][2] + bb[2];
        o.w = acc[i][3] + bb[3];
        *(float4 *)(out + (size_t)bt * HH + h0 + sn * 4) = o;
    }
}

extern "C" void kernel_launch(void *const *d_in, const int *in_sizes, int n_in,
                              void *d_out, int out_size) {
    const float *seq = (const float *)d_in[0];
    const float *W_in = (const float *)d_in[1];
    const float *b_in = (const float *)d_in[2];
    const float *W_rec = (const float *)d_in[3];
    const float *bias = (const float *)d_in[4];
    const float *tau = (const float *)d_in[5];
    float *out = (float *)d_out;

    cudaFuncSetAttribute(proj_kernel, cudaFuncAttributeMaxDynamicSharedMemorySize,
                         PROJ_SMEM_FLOATS * (int)sizeof(float));
    cudaFuncSetAttribute(scan_mma, cudaFuncAttributeMaxDynamicSharedMemorySize,
                         SMEM_TOTAL);

    proj_kernel<<<dim3(BT / PM, HH / PN), 256, PROJ_SMEM_FLOATS * sizeof(float)>>>(
        seq, W_in, b_in, bias, out);
    scan_mma<<<GRID, NTHR, SMEM_TOTAL>>>(W_rec, tau, out);
}

// round 11
// speedup vs baseline: 2.4246x; 1.0423x over previous
#include <cuda_runtime.h>
#include <cuda_bf16.h>
#include <cstdint>

// Problem dims
#define BB 64
#define TT 512
#define HH 1024
#define DD 128
#define BT (BB * TT)

// ---------------- Scan config ----------------
#define GRID 128        // 4 batch-groups x 32 col-groups, 1 CTA/SM co-resident
#define NTHR 512        // 16 warps: warp w -> (kchunk w>>1, col-half w&1)
#define MB 16
#define NB 32

#define PITCH_H 2064    // bytes per staged h row (1024 bf16 + 8 pad)
#define OFF_H1 0
#define OFF_H2 33024
#define OFF_ZR 66048
#define ZP 36           // zred row pitch (floats)
#define OFF_HS 84480
#define SMEM_TOTAL 86528

// ---------------- Projection config ----------------
#define PM 64
#define PN 64
#define APAD 68
#define PROJ_SMEM_FLOATS (DD * APAD + DD * PN)

// Scratch (persists across graph replays; deterministic per replay)
__device__ __align__(16) __nv_bfloat16 g_hs[2][2][BB][HH];  // [buf][split][b][k]
// Per-CTA progress flags, one 128B line each. Monotonic; +TT per replay (uniform).
__device__ unsigned g_flags[4][32][32];

// ======================= helpers =======================
__device__ __forceinline__ void mma16816(float *d, const uint32_t *a, const uint32_t *b) {
    asm volatile(
        "mma.sync.aligned.m16n8k16.row.col.f32.bf16.bf16.f32 "
        "{%0,%1,%2,%3}, {%4,%5,%6,%7}, {%8,%9}, {%0,%1,%2,%3};"
        : "+f"(d[0]), "+f"(d[1]), "+f"(d[2]), "+f"(d[3])
        : "r"(a[0]), "r"(a[1]), "r"(a[2]), "r"(a[3]), "r"(b[0]), "r"(b[1]));
}

__device__ __forceinline__ void ldsm_x4(uint32_t *r, uint32_t addr) {
    asm volatile("ldmatrix.sync.aligned.m8n8.x4.shared.b16 {%0,%1,%2,%3}, [%4];"
        : "=r"(r[0]), "=r"(r[1]), "=r"(r[2]), "=r"(r[3]) : "r"(addr));
}

#define CP_ASYNC16(dst, src) \
    asm volatile("cp.async.cg.shared.global [%0], [%1], 16;" :: "r"(dst), "l"(src))
#define CP_COMMIT() asm volatile("cp.async.commit_group;")
#define CP_WAIT(n)  asm volatile("cp.async.wait_group %0;" :: "n"(n))

// Split fp32 pair -> (primary bf16x2, residual bf16x2)
__device__ __forceinline__ void split2(float x, float y, uint32_t &p, uint32_t &r) {
    __nv_bfloat16 px = __float2bfloat16(x), py = __float2bfloat16(y);
    __nv_bfloat16 rx = __float2bfloat16(x - __bfloat162float(px));
    __nv_bfloat16 ry = __float2bfloat16(y - __bfloat162float(py));
    p = (uint32_t)__bfloat16_as_ushort(px) | ((uint32_t)__bfloat16_as_ushort(py) << 16);
    r = (uint32_t)__bfloat16_as_ushort(rx) | ((uint32_t)__bfloat16_as_ushort(ry) << 16);
}

// =====================================================================
// Persistent HMMA scan: z[b][n] = u_t[b][n] + sum_k h[b][k] W[n][k]
// Group-local flag barrier (32 same-gm CTAs). cp.async double-buffered
// staging overlaps L2 latency with first-half MMA. All spins bounded.
// =====================================================================
__global__ void __launch_bounds__(NTHR, 1)
scan_mma(const float *__restrict__ W_rec, const float *__restrict__ taup,
         float *__restrict__ out) {
    extern __shared__ char smem[];
    const uint32_t sb = (uint32_t)__cvta_generic_to_shared(smem);
    const int tid = threadIdx.x;
    const int wid = tid >> 5;
    const int lane = tid & 31;
    const int cta = blockIdx.x;
    const int gm = cta >> 5;        // 0..3
    const int gn = cta & 31;        // 0..31
    const int b0 = gm * MB;
    const int n0 = gn * NB;
    const float inv_tau = 1.0f / (*taup);

    const int nh = wid & 1;         // column half -> cols nh*16..+16
    const int kw = wid >> 1;        // K-chunk id (0..7)
    const int kc = kw * 128;
    const int lq = lane >> 2;       // 0..7
    const int lr = lane & 3;        // 0..3

    const unsigned base = *(volatile unsigned *)&g_flags[gm][gn][0];

    // ---- One-time: W slice fragments -> registers (bf16 split pair) ----
    uint32_t Wr1[8][2][2], Wr2[8][2][2];
    #pragma unroll
    for (int ks = 0; ks < 8; ++ks) {
        #pragma unroll
        for (int nt = 0; nt < 2; ++nt) {
            const float *wrow = W_rec + (size_t)(n0 + nh * 16 + nt * 8 + lq) * HH
                                + kc + ks * 16 + 2 * lr;
            split2(wrow[0], wrow[1], Wr1[ks][nt][0], Wr2[ks][nt][0]);
            split2(wrow[8], wrow[9], Wr1[ks][nt][1], Wr2[ks][nt][1]);
        }
    }

    // ---- One-time: zero fp32 h slice (smem) and bf16 split buf0 (gmem) ----
    float *hs = (float *)(smem + OFF_HS);
    const int ob = tid >> 5, on = tid & 31;
    hs[tid] = 0.0f;
    {
        __nv_bfloat16 z = __float2bfloat16(0.0f);
        g_hs[0][0][b0 + ob][n0 + on] = z;
        g_hs[0][1][b0 + ob][n0 + on] = z;
    }

    // publish "init done" = base + 1 (single-thread fence: cumulative)
    __syncthreads();
    if (tid == 0) { __threadfence(); atomicExch(&g_flags[gm][gn][0], base + 1u); }

    float *zr = (float *)(smem + OFF_ZR);
    const uint32_t ab1 = sb + OFF_H1 +
        (uint32_t)((lane & 15) * PITCH_H + (lane >> 4) * 16 + kc * 2);
    const uint32_t ab2 = ab1 + (OFF_H2 - OFF_H1);

    const int bg = b0 + ob, ng = n0 + on;
    size_t oidx = (size_t)bg * TT * HH + ng;
    volatile unsigned *myflag_row = &g_flags[gm][0][0];

    // u carried one step ahead (u_proj for step t is untouched until step t)
    float u_cur = __ldcg(out + oidx);

    for (int t = 0; t < TT; ++t) {
        const int rb = t & 1;
        const int nb = rb ^ 1;

        // ---- Wait: 32 group flags >= base+t+1 (parallel, bounded) ----
        if (wid == 0) {
            const unsigned target = base + (unsigned)t + 1u;
            volatile unsigned *fp = myflag_row + lane * 32;
            unsigned c = 0;
            while ((int)(*fp - target) < 0) {
                if (++c > (1u << 26)) break;
                if (c > 4096u) __nanosleep(64);
            }
            __threadfence();   // acquire (cumulative through the bar below)
        }
        __syncthreads();

        // ---- Stage h slice via cp.async: group A = k<512, group B = k>=512 ----
        const __nv_bfloat16 *hb = &g_hs[rb][0][0][0];
        #pragma unroll
        for (int i = 0; i < 4; ++i) {
            int id = i * NTHR + tid;            // 0..2047
            int row = id >> 6;                  // 0..31: split=row>>4, b=row&15
            int c16 = id & 63;
            const void *src = hb + ((row >> 4) * (BB * HH)) + (b0 + (row & 15)) * HH + c16 * 8;
            uint32_t dst = sb + (row >> 4 ? OFF_H2 : OFF_H1)
                           + (row & 15) * PITCH_H + c16 * 16;
            CP_ASYNC16(dst, src);
        }
        CP_COMMIT();
        #pragma unroll
        for (int i = 0; i < 4; ++i) {
            int id = i * NTHR + tid;
            int row = id >> 6;
            int c16 = (id & 63) + 64;
            const void *src = hb + ((row >> 4) * (BB * HH)) + (b0 + (row & 15)) * HH + c16 * 8;
            uint32_t dst = sb + (row >> 4 ? OFF_H2 : OFF_H1)
                           + (row & 15) * PITCH_H + c16 * 16;
            CP_ASYNC16(dst, src);
        }
        CP_COMMIT();

        // prefetch next step's u while copies fly
        float u_next = 0.0f;
        if (t < TT - 1) u_next = __ldcg(out + oidx + HH);

        float D[2][4];
        #pragma unroll
        for (int nt = 0; nt < 2; ++nt)
            #pragma unroll
            for (int j = 0; j < 4; ++j) D[nt][j] = 0.0f;

        CP_WAIT(1);            // group A landed
        __syncthreads();

        // ---- first-half MMA (kw<4, i.e. k<512) overlaps group-B copies ----
        if (wid < 8) {
            #pragma unroll
            for (int ks = 0; ks < 8; ++ks) {
                uint32_t a1[4], a2[4];
                ldsm_x4(a1, ab1 + ks * 32);
                ldsm_x4(a2, ab2 + ks * 32);
                #pragma unroll
                for (int nt = 0; nt < 2; ++nt) {
                    mma16816(D[nt], a1, Wr1[ks][nt]);
                    mma16816(D[nt], a1, Wr2[ks][nt]);
                    mma16816(D[nt], a2, Wr1[ks][nt]);
                }
            }
        }

        CP_WAIT(0);            // group B landed
        __syncthreads();

        if (wid >= 8) {
            #pragma unroll
            for (int ks = 0; ks < 8; ++ks) {
                uint32_t a1[4], a2[4];
                ldsm_x4(a1, ab1 + ks * 32);
                ldsm_x4(a2, ab2 + ks * 32);
                #pragma unroll
                for (int nt = 0; nt < 2; ++nt) {
                    mma16816(D[nt], a1, Wr1[ks][nt]);
                    mma16816(D[nt], a1, Wr2[ks][nt]);
                    mma16816(D[nt], a2, Wr1[ks][nt]);
                }
            }
        }

        // ---- k-split partials -> smem zred[8][16][ZP] ----
        {
            int zb = kw * (16 * ZP) + lq * ZP + nh * 16 + 2 * lr;
            #pragma unroll
            for (int nt = 0; nt < 2; ++nt) {
                zr[zb + nt * 8]     = D[nt][0];
                zr[zb + nt * 8 + 1] = D[nt][1];
                zr[zb + 8 * ZP + nt * 8]     = D[nt][2];
                zr[zb + 8 * ZP + nt * 8 + 1] = D[nt][3];
            }
        }
        __syncthreads();

        // ---- Epilogue: h' = h + (tanh(u+z)-h)/tau; publish BEFORE out-store ----
        float s = 0.0f;
        #pragma unroll
        for (int q = 0; q < 8; ++q) s += zr[q * (16 * ZP) + ob * ZP + on];
        float hp = hs[tid];
        float f = tanhf(u_cur + s);
        float hn = hp + (f - hp) * inv_tau;
        {
            __nv_bfloat16 h1 = __float2bfloat16(hn);
            __nv_bfloat16 h2 = __float2bfloat16(hn - __bfloat162float(h1));
            g_hs[nb][0][bg][ng] = h1;
            g_hs[nb][1][bg][ng] = h2;
        }
        __syncthreads();
        if (t < TT - 1 && tid == 0) {
            __threadfence();   // cumulative release of all threads' h stores
            atomicExch(&g_flags[gm][gn][0], base + (unsigned)t + 2u);
        }

        // off-critical-path stores
        out[oidx] = hn;
        hs[tid] = hn;
        if (t == TT - 1)
            out[(size_t)BB * TT * HH + (size_t)bg * HH + ng] = hn;

        u_cur = u_next;
        oidx += HH;
    }
}

// =====================================================================
// Projection kernel: u[bt][h] = seq[bt]·W_in[h] + b_in[h] + bias[h]
// =====================================================================
__global__ void __launch_bounds__(256, 2)
proj_kernel(const float *__restrict__ seq, const float *__restrict__ W_in,
            const float *__restrict__ b_in, const float *__restrict__ bias,
            float *__restrict__ out) {
    extern __shared__ char smemp[];
    float *A_s = (float *)smemp;
    float *B_s = (float *)smemp + DD * APAD;

    const int tid = threadIdx.x;
    const int bt0 = blockIdx.x * PM;
    const int h0 = blockIdx.y * PN;

    {
        const int m = tid & 63;
        const int kg = tid >> 6;
        const float *arow = seq + (size_t)(bt0 + m) * DD;
        const float *brow = W_in + (size_t)(h0 + m) * DD;
        #pragma unroll
        for (int it = 0; it < 8; ++it) {
            int c = kg + it * 4;
            float4 a = *(const float4 *)(arow + c * 4);
            float4 w = *(const float4 *)(brow + c * 4);
            int k = c * 4;
            A_s[(k + 0) * APAD + m] = a.x; A_s[(k + 1) * APAD + m] = a.y;
            A_s[(k + 2) * APAD + m] = a.z; A_s[(k + 3) * APAD + m] = a.w;
            B_s[(k + 0) * PN + m] = w.x; B_s[(k + 1) * PN + m] = w.y;
            B_s[(k + 2) * PN + m] = w.z; B_s[(k + 3) * PN + m] = w.w;
        }
    }
    __syncthreads();

    const int smi = tid & 15;
    const int sn = tid >> 4;
    float acc[4][4];
    #pragma unroll
    for (int i = 0; i < 4; ++i)
        #pragma unroll
        for (int j = 0; j < 4; ++j) acc[i][j] = 0.0f;

    const float *ap = A_s + smi * 4;
    const float *bp = B_s + sn * 4;
    #pragma unroll 8
    for (int k = 0; k < DD; ++k) {
        float4 av = *(const float4 *)(ap + k * APAD);
        float4 bv = *(const float4 *)(bp + k * PN);
        acc[0][0] += av.x * bv.x; acc[0][1] += av.x * bv.y;
        acc[0][2] += av.x * bv.z; acc[0][3] += av.x * bv.w;
        acc[1][0] += av.y * bv.x; acc[1][1] += av.y * bv.y;
        acc[1][2] += av.y * bv.z; acc[1][3] += av.y * bv.w;
        acc[2][0] += av.z * bv.x; acc[2][1] += av.z * bv.y;
        acc[2][2] += av.z * bv.z; acc[2][3] += av.z * bv.w;
        acc[3][0] += av.w * bv.x; acc[3][1] += av.w * bv.y;
        acc[3][2] += av.w * bv.z; acc[3][3] += av.w * bv.w;
    }

    float bb[4];
    #pragma unroll
    for (int j = 0; j < 4; ++j)
        bb[j] = b_in[h0 + sn * 4 + j] + bias[h0 + sn * 4 + j];

    #pragma unroll
    for (int i = 0; i < 4; ++i) {
        int bt = bt0 + smi * 4 + i;
        float4 o;
        o.x = acc[i][0] + bb[0];
        o.y = acc[i][1] + bb[1];
        o.z = acc[i][2] + bb[2];
        o.w = acc[i][3] + bb[3];
        *(float4 *)(out + (size_t)bt * HH + h0 + sn * 4) = o;
    }
}

extern "C" void kernel_launch(void *const *d_in, const int *in_sizes, int n_in,
                              void *d_out, int out_size) {
    const float *seq = (const float *)d_in[0];
    const float *W_in = (const float *)d_in[1];
    const float *b_in = (const float *)d_in[2];
    const float *W_rec = (const float *)d_in[3];
    const float *bias = (const float *)d_in[4];
    const float *tau = (const float *)d_in[5];
    float *out = (float *)d_out;

    cudaFuncSetAttribute(proj_kernel, cudaFuncAttributeMaxDynamicSharedMemorySize,
                         PROJ_SMEM_FLOATS * (int)sizeof(float));
    cudaFuncSetAttribute(scan_mma, cudaFuncAttributeMaxDynamicSharedMemorySize,
                         SMEM_TOTAL);

    proj_kernel<<<dim3(BT / PM, HH / PN), 256, PROJ_SMEM_FLOATS * sizeof(float)>>>(
        seq, W_in, b_in, bias, out);
    scan_mma<<<GRID, NTHR, SMEM_TOTAL>>>(W_rec, tau, out);
}

// round 13
// speedup vs baseline: 2.7313x; 1.1265x over previous
#include <cuda_runtime.h>
#include <cuda_bf16.h>
#include <cstdint>

// Problem dims
#define BB 64
#define TT 512
#define HH 1024
#define DD 128
#define BT (BB * TT)

// ---------------- Scan config (R11-proven) ----------------
#define GRID 128
#define NTHR 512
#define MB 16
#define NB 32

#define PITCH_H 2064
#define OFF_H1 0
#define OFF_H2 33024
#define OFF_ZR 66048
#define ZP 36
#define OFF_HS 84480
#define SMEM_TOTAL 86528

// ---------------- Projection (HMMA) config ----------------
#define P2M 128
#define P2N 64
#define PA 272                      // 256B row + 16B skew (ldmatrix conflict-free)
#define POF_A1 0
#define POF_A2 (128 * PA)           // 34816
#define POF_W1 (2 * 128 * PA)       // 69632
#define POF_W2 (POF_W1 + 64 * PA)   // 87040
#define PROJ_SMEM (POF_W2 + 64 * PA)  // 104448

// Scratch (persists across graph replays; deterministic per replay)
__device__ __align__(16) __nv_bfloat16 g_hs[2][2][BB][HH];  // [buf][split][b][k]
__device__ unsigned g_flags[4][32][32];

// ======================= helpers =======================
__device__ __forceinline__ void mma16816(float *d, const uint32_t *a, const uint32_t *b) {
    asm volatile(
        "mma.sync.aligned.m16n8k16.row.col.f32.bf16.bf16.f32 "
        "{%0,%1,%2,%3}, {%4,%5,%6,%7}, {%8,%9}, {%0,%1,%2,%3};"
        : "+f"(d[0]), "+f"(d[1]), "+f"(d[2]), "+f"(d[3])
        : "r"(a[0]), "r"(a[1]), "r"(a[2]), "r"(a[3]), "r"(b[0]), "r"(b[1]));
}

__device__ __forceinline__ void ldsm_x4(uint32_t *r, uint32_t addr) {
    asm volatile("ldmatrix.sync.aligned.m8n8.x4.shared.b16 {%0,%1,%2,%3}, [%4];"
        : "=r"(r[0]), "=r"(r[1]), "=r"(r[2]), "=r"(r[3]) : "r"(addr));
}

#define CP_ASYNC16(dst, src) \
    asm volatile("cp.async.cg.shared.global [%0], [%1], 16;" :: "r"(dst), "l"(src))
#define CP_COMMIT() asm volatile("cp.async.commit_group;")
#define CP_WAIT(n)  asm volatile("cp.async.wait_group %0;" :: "n"(n))

// Split fp32 pair -> (primary bf16x2, residual bf16x2)
__device__ __forceinline__ void split2(float x, float y, uint32_t &p, uint32_t &r) {
    __nv_bfloat16 px = __float2bfloat16(x), py = __float2bfloat16(y);
    __nv_bfloat16 rx = __float2bfloat16(x - __bfloat162float(px));
    __nv_bfloat16 ry = __float2bfloat16(y - __bfloat162float(py));
    p = (uint32_t)__bfloat16_as_ushort(px) | ((uint32_t)__bfloat16_as_ushort(py) << 16);
    r = (uint32_t)__bfloat16_as_ushort(rx) | ((uint32_t)__bfloat16_as_ushort(ry) << 16);
}

// =====================================================================
// Persistent HMMA scan — EXACT R11-proven version (2353us total).
// =====================================================================
__global__ void __launch_bounds__(NTHR, 1)
scan_mma(const float *__restrict__ W_rec, const float *__restrict__ taup,
         float *__restrict__ out) {
    extern __shared__ char smem[];
    const uint32_t sb = (uint32_t)__cvta_generic_to_shared(smem);
    const int tid = threadIdx.x;
    const int wid = tid >> 5;
    const int lane = tid & 31;
    const int cta = blockIdx.x;
    const int gm = cta >> 5;
    const int gn = cta & 31;
    const int b0 = gm * MB;
    const int n0 = gn * NB;
    const float inv_tau = 1.0f / (*taup);

    const int nh = wid & 1;
    const int kw = wid >> 1;
    const int kc = kw * 128;
    const int lq = lane >> 2;
    const int lr = lane & 3;

    const unsigned base = *(volatile unsigned *)&g_flags[gm][gn][0];

    uint32_t Wr1[8][2][2], Wr2[8][2][2];
    #pragma unroll
    for (int ks = 0; ks < 8; ++ks) {
        #pragma unroll
        for (int nt = 0; nt < 2; ++nt) {
            const float *wrow = W_rec + (size_t)(n0 + nh * 16 + nt * 8 + lq) * HH
                                + kc + ks * 16 + 2 * lr;
            split2(wrow[0], wrow[1], Wr1[ks][nt][0], Wr2[ks][nt][0]);
            split2(wrow[8], wrow[9], Wr1[ks][nt][1], Wr2[ks][nt][1]);
        }
    }

    float *hs = (float *)(smem + OFF_HS);
    const int ob = tid >> 5, on = tid & 31;
    hs[tid] = 0.0f;
    {
        __nv_bfloat16 z = __float2bfloat16(0.0f);
        g_hs[0][0][b0 + ob][n0 + on] = z;
        g_hs[0][1][b0 + ob][n0 + on] = z;
    }

    __syncthreads();
    if (tid == 0) { __threadfence(); atomicExch(&g_flags[gm][gn][0], base + 1u); }

    float *zr = (float *)(smem + OFF_ZR);
    const uint32_t ab1 = sb + OFF_H1 +
        (uint32_t)((lane & 15) * PITCH_H + (lane >> 4) * 16 + kc * 2);
    const uint32_t ab2 = ab1 + (OFF_H2 - OFF_H1);

    const int bg = b0 + ob, ng = n0 + on;
    size_t oidx = (size_t)bg * TT * HH + ng;
    volatile unsigned *myflag_row = &g_flags[gm][0][0];

    float u_cur = __ldcg(out + oidx);

    for (int t = 0; t < TT; ++t) {
        const int rb = t & 1;
        const int nb = rb ^ 1;

        if (wid == 0) {
            const unsigned target = base + (unsigned)t + 1u;
            volatile unsigned *fp = myflag_row + lane * 32;
            unsigned c = 0;
            while ((int)(*fp - target) < 0) {
                if (++c > (1u << 26)) break;
                if (c > 4096u) __nanosleep(64);
            }
            __threadfence();
        }
        __syncthreads();

        const __nv_bfloat16 *hb = &g_hs[rb][0][0][0];
        #pragma unroll
        for (int i = 0; i < 4; ++i) {
            int id = i * NTHR + tid;
            int row = id >> 6;
            int c16 = id & 63;
            const void *src = hb + ((row >> 4) * (BB * HH)) + (b0 + (row & 15)) * HH + c16 * 8;
            uint32_t dst = sb + (row >> 4 ? OFF_H2 : OFF_H1)
                           + (row & 15) * PITCH_H + c16 * 16;
            CP_ASYNC16(dst, src);
        }
        CP_COMMIT();
        #pragma unroll
        for (int i = 0; i < 4; ++i) {
            int id = i * NTHR + tid;
            int row = id >> 6;
            int c16 = (id & 63) + 64;
            const void *src = hb + ((row >> 4) * (BB * HH)) + (b0 + (row & 15)) * HH + c16 * 8;
            uint32_t dst = sb + (row >> 4 ? OFF_H2 : OFF_H1)
                           + (row & 15) * PITCH_H + c16 * 16;
            CP_ASYNC16(dst, src);
        }
        CP_COMMIT();

        float u_next = 0.0f;
        if (t < TT - 1) u_next = __ldcg(out + oidx + HH);

        float D[2][4];
        #pragma unroll
        for (int nt = 0; nt < 2; ++nt)
            #pragma unroll
            for (int j = 0; j < 4; ++j) D[nt][j] = 0.0f;

        CP_WAIT(1);
        __syncthreads();

        if (wid < 8) {
            #pragma unroll
            for (int ks = 0; ks < 8; ++ks) {
                uint32_t a1[4], a2[4];
                ldsm_x4(a1, ab1 + ks * 32);
                ldsm_x4(a2, ab2 + ks * 32);
                #pragma unroll
                for (int nt = 0; nt < 2; ++nt) {
                    mma16816(D[nt], a1, Wr1[ks][nt]);
                    mma16816(D[nt], a1, Wr2[ks][nt]);
                    mma16816(D[nt], a2, Wr1[ks][nt]);
                }
            }
        }

        CP_WAIT(0);
        __syncthreads();

        if (wid >= 8) {
            #pragma unroll
            for (int ks = 0; ks < 8; ++ks) {
                uint32_t a1[4], a2[4];
                ldsm_x4(a1, ab1 + ks * 32);
                ldsm_x4(a2, ab2 + ks * 32);
                #pragma unroll
                for (int nt = 0; nt < 2; ++nt) {
                    mma16816(D[nt], a1, Wr1[ks][nt]);
                    mma16816(D[nt], a1, Wr2[ks][nt]);
                    mma16816(D[nt], a2, Wr1[ks][nt]);
                }
            }
        }

        {
            int zb = kw * (16 * ZP) + lq * ZP + nh * 16 + 2 * lr;
            #pragma unroll
            for (int nt = 0; nt < 2; ++nt) {
                zr[zb + nt * 8]     = D[nt][0];
                zr[zb + nt * 8 + 1] = D[nt][1];
                zr[zb + 8 * ZP + nt * 8]     = D[nt][2];
                zr[zb + 8 * ZP + nt * 8 + 1] = D[nt][3];
            }
        }
        __syncthreads();

        float s = 0.0f;
        #pragma unroll
        for (int q = 0; q < 8; ++q) s += zr[q * (16 * ZP) + ob * ZP + on];
        float hp = hs[tid];
        float f = tanhf(u_cur + s);
        float hn = hp + (f - hp) * inv_tau;
        {
            __nv_bfloat16 h1 = __float2bfloat16(hn);
            __nv_bfloat16 h2 = __float2bfloat16(hn - __bfloat162float(h1));
            g_hs[nb][0][bg][ng] = h1;
            g_hs[nb][1][bg][ng] = h2;
        }
        __syncthreads();
        if (t < TT - 1 && tid == 0) {
            __threadfence();
            atomicExch(&g_flags[gm][gn][0], base + (unsigned)t + 2u);
        }

        out[oidx] = hn;
        hs[tid] = hn;
        if (t == TT - 1)
            out[(size_t)BB * TT * HH + (size_t)bg * HH + ng] = hn;

        u_cur = u_next;
        oidx += HH;
    }
}

// =====================================================================
// Projection (HMMA): u[bt][h] = seq[bt]·W_in[h] + b_in[h] + bias[h]
// CTA tile 128x64xK128; 8 warps (4m x 2n); bf16-split 3-term product.
// Both operands staged in smem; A and B fragments via ldmatrix.
// =====================================================================
__global__ void __launch_bounds__(256, 2)
proj_mma(const float *__restrict__ seq, const float *__restrict__ W_in,
         const float *__restrict__ b_in, const float *__restrict__ bias,
         float *__restrict__ out) {
    extern __shared__ char sm[];
    const uint32_t sb = (uint32_t)__cvta_generic_to_shared(sm);
    const int tid = threadIdx.x;
    const int wid = tid >> 5;
    const int lane = tid & 31;
    const int bt0 = blockIdx.x * P2M;
    const int h0 = blockIdx.y * P2N;
    const int wm = wid & 3;         // row group: rows wm*32..+32
    const int wn = wid >> 2;        // col group: cols wn*32..+32

    // ---- Stage seq tile [128][128] fp32 -> bf16 split pair ----
    #pragma unroll
    for (int i = 0; i < 16; ++i) {
        int id = tid + i * 256;     // 0..4095 float4s
        int row = id >> 5;          // 0..127
        int c4 = id & 31;           // 0..31 (4 floats each)
        float4 v = *(const float4 *)(seq + (size_t)(bt0 + row) * DD + c4 * 4);
        uint32_t p0, r0, p1, r1;
        split2(v.x, v.y, p0, r0);
        split2(v.z, v.w, p1, r1);
        *(uint2 *)(sm + POF_A1 + row * PA + c4 * 8) = make_uint2(p0, p1);
        *(uint2 *)(sm + POF_A2 + row * PA + c4 * 8) = make_uint2(r0, r1);
    }
    // ---- Stage W_in tile [64][128] ----
    #pragma unroll
    for (int i = 0; i < 8; ++i) {
        int id = tid + i * 256;     // 0..2047
        int row = id >> 5;          // 0..63
        int c4 = id & 31;
        float4 v = *(const float4 *)(W_in + (size_t)(h0 + row) * DD + c4 * 4);
        uint32_t p0, r0, p1, r1;
        split2(v.x, v.y, p0, r0);
        split2(v.z, v.w, p1, r1);
        *(uint2 *)(sm + POF_W1 + row * PA + c4 * 8) = make_uint2(p0, p1);
        *(uint2 *)(sm + POF_W2 + row * PA + c4 * 8) = make_uint2(r0, r1);
    }
    __syncthreads();

    // Fragment address bases
    const uint32_t aA = sb + POF_A1 +
        (uint32_t)((wm * 32 + (lane & 15)) * PA + (lane >> 4) * 16);
    const uint32_t aW = sb + POF_W1 +
        (uint32_t)((wn * 32 + ((lane >> 4) & 1) * 8 + (lane & 7)) * PA
                   + ((lane >> 3) & 1) * 16);

    float D[2][4][4];
    #pragma unroll
    for (int mt = 0; mt < 2; ++mt)
        #pragma unroll
        for (int nt = 0; nt < 4; ++nt)
            #pragma unroll
            for (int j = 0; j < 4; ++j) D[mt][nt][j] = 0.0f;

    #pragma unroll
    for (int ks = 0; ks < 8; ++ks) {
        uint32_t a1[2][4], a2[2][4];
        ldsm_x4(a1[0], aA + ks * 32);
        ldsm_x4(a1[1], aA + 16 * PA + ks * 32);
        ldsm_x4(a2[0], aA + (POF_A2 - POF_A1) + ks * 32);
        ldsm_x4(a2[1], aA + (POF_A2 - POF_A1) + 16 * PA + ks * 32);
        uint32_t b1[8], b2[8];
        ldsm_x4(b1,     aW + ks * 32);                        // n-octets 0,1
        ldsm_x4(b1 + 4, aW + 16 * PA + ks * 32);              // n-octets 2,3
        ldsm_x4(b2,     aW + (POF_W2 - POF_W1) + ks * 32);
        ldsm_x4(b2 + 4, aW + (POF_W2 - POF_W1) + 16 * PA + ks * 32);
        #pragma unroll
        for (int mt = 0; mt < 2; ++mt)
            #pragma unroll
            for (int nt = 0; nt < 4; ++nt) {
                mma16816(D[mt][nt], a1[mt], &b1[nt * 2]);
                mma16816(D[mt][nt], a1[mt], &b2[nt * 2]);
                mma16816(D[mt][nt], a2[mt], &b1[nt * 2]);
            }
    }

    // ---- Epilogue: add b_in+bias, write fp32 ----
    #pragma unroll
    for (int nt = 0; nt < 4; ++nt) {
        int col = h0 + wn * 32 + nt * 8 + 2 * (lane & 3);
        float2 bi = *(const float2 *)(b_in + col);
        float2 bs = *(const float2 *)(bias + col);
        float bb0 = bi.x + bs.x, bb1 = bi.y + bs.y;
        #pragma unroll
        for (int mt = 0; mt < 2; ++mt) {
            int row0 = bt0 + wm * 32 + mt * 16 + (lane >> 2);
            *(float2 *)(out + (size_t)row0 * HH + col) =
                make_float2(D[mt][nt][0] + bb0, D[mt][nt][1] + bb1);
            *(float2 *)(out + (size_t)(row0 + 8) * HH + col) =
                make_float2(D[mt][nt][2] + bb0, D[mt][nt][3] + bb1);
        }
    }
}

extern "C" void kernel_launch(void *const *d_in, const int *in_sizes, int n_in,
                              void *d_out, int out_size) {
    const float *seq = (const float *)d_in[0];
    const float *W_in = (const float *)d_in[1];
    const float *b_in = (const float *)d_in[2];
    const float *W_rec = (const float *)d_in[3];
    const float *bias = (const float *)d_in[4];
    const float *tau = (const float *)d_in[5];
    float *out = (float *)d_out;

    cudaFuncSetAttribute(proj_mma, cudaFuncAttributeMaxDynamicSharedMemorySize,
                         PROJ_SMEM);
    cudaFuncSetAttribute(scan_mma, cudaFuncAttributeMaxDynamicSharedMemorySize,
                         SMEM_TOTAL);

    proj_mma<<<dim3(BT / P2M, HH / P2N), 256, PROJ_SMEM>>>(
        seq, W_in, b_in, bias, out);
    scan_mma<<<GRID, NTHR, SMEM_TOTAL>>>(W_rec, tau, out);
}

// round 16
// speedup vs baseline: 3.1694x; 1.1604x over previous
#include <cuda_runtime.h>
#include <cuda_bf16.h>
#include <cuda_fp16.h>
#include <cstdint>

// Problem dims
#define BB 64
#define TT 512
#define HH 1024
#define DD 128
#define BT (BB * TT)

// ---------------- Scan config ----------------
#define GRID 128
#define NTHR 512
#define MB 16
#define NB 32

#define PITCH_H 2064           // 1024 fp16 (2048B) + 16B skew
#define OFF_H 0                // [16][PITCH_H] staged h tile
#define OFF_ZR 33024           // zred [8][16][ZP] floats
#define ZP 36
#define OFF_HS 51456           // local fp32 h [512]
#define SMEM_TOTAL 53504

// ---------------- Projection (HMMA) config ----------------
#define P2M 128
#define P2N 64
#define PA 272
#define POF_A1 0
#define POF_A2 (128 * PA)
#define POF_W1 (2 * 128 * PA)
#define POF_W2 (POF_W1 + 64 * PA)
#define PROJ_SMEM (POF_W2 + 64 * PA)

// Scratch (persists across graph replays; deterministic per replay)
__device__ __align__(16) __half g_h16[2][BB][HH];   // [buf][b][k] fp16 h
__device__ unsigned g_flags[4][32][32];

// ======================= helpers =======================
// bf16 MMA (projection kernel)
__device__ __forceinline__ void mma16816(float *d, const uint32_t *a, const uint32_t *b) {
    asm volatile(
        "mma.sync.aligned.m16n8k16.row.col.f32.bf16.bf16.f32 "
        "{%0,%1,%2,%3}, {%4,%5,%6,%7}, {%8,%9}, {%0,%1,%2,%3};"
        : "+f"(d[0]), "+f"(d[1]), "+f"(d[2]), "+f"(d[3])
        : "r"(a[0]), "r"(a[1]), "r"(a[2]), "r"(a[3]), "r"(b[0]), "r"(b[1]));
}
// fp16 MMA (scan kernel)
__device__ __forceinline__ void mma16816h(float *d, const uint32_t *a, const uint32_t *b) {
    asm volatile(
        "mma.sync.aligned.m16n8k16.row.col.f32.f16.f16.f32 "
        "{%0,%1,%2,%3}, {%4,%5,%6,%7}, {%8,%9}, {%0,%1,%2,%3};"
        : "+f"(d[0]), "+f"(d[1]), "+f"(d[2]), "+f"(d[3])
        : "r"(a[0]), "r"(a[1]), "r"(a[2]), "r"(a[3]), "r"(b[0]), "r"(b[1]));
}

__device__ __forceinline__ void ldsm_x4(uint32_t *r, uint32_t addr) {
    asm volatile("ldmatrix.sync.aligned.m8n8.x4.shared.b16 {%0,%1,%2,%3}, [%4];"
        : "=r"(r[0]), "=r"(r[1]), "=r"(r[2]), "=r"(r[3]) : "r"(addr));
}

#define CP_ASYNC16(dst, src) \
    asm volatile("cp.async.cg.shared.global [%0], [%1], 16;" :: "r"(dst), "l"(src))
#define CP_COMMIT() asm volatile("cp.async.commit_group;")
#define CP_WAIT(n)  asm volatile("cp.async.wait_group %0;" :: "n"(n))

// fp32 pair -> (primary bf16x2, residual bf16x2) — projection
__device__ __forceinline__ void split2(float x, float y, uint32_t &p, uint32_t &r) {
    __nv_bfloat16 px = __float2bfloat16(x), py = __float2bfloat16(y);
    __nv_bfloat16 rx = __float2bfloat16(x - __bfloat162float(px));
    __nv_bfloat16 ry = __float2bfloat16(y - __bfloat162float(py));
    p = (uint32_t)__bfloat16_as_ushort(px) | ((uint32_t)__bfloat16_as_ushort(py) << 16);
    r = (uint32_t)__bfloat16_as_ushort(rx) | ((uint32_t)__bfloat16_as_ushort(ry) << 16);
}
// fp32 pair -> (primary fp16x2, residual fp16x2) — scan W
__device__ __forceinline__ void split2h(float x, float y, uint32_t &p, uint32_t &r) {
    __half px = __float2half(x), py = __float2half(y);
    __half rx = __float2half(x - __half2float(px));
    __half ry = __float2half(y - __half2float(py));
    p = (uint32_t)__half_as_ushort(px) | ((uint32_t)__half_as_ushort(py) << 16);
    r = (uint32_t)__half_as_ushort(rx) | ((uint32_t)__half_as_ushort(ry) << 16);
}

// =====================================================================
// Persistent HMMA scan — R13-proven STRUCTURE verbatim (warp0-poll,
// two cp.async groups, CP_WAIT(1)/(0), two-phase MMA, 5 syncs/step).
// Only change: h is fp16 single (not bf16 split pair); W fp16-split in
// registers; 2-term product. Staged bytes halved (32KB/step).
// =====================================================================
__global__ void __launch_bounds__(NTHR, 1)
scan_mma(const float *__restrict__ W_rec, const float *__restrict__ taup,
         float *__restrict__ out) {
    extern __shared__ char smem[];
    const uint32_t sb = (uint32_t)__cvta_generic_to_shared(smem);
    const int tid = threadIdx.x;
    const int wid = tid >> 5;
    const int lane = tid & 31;
    const int cta = blockIdx.x;
    const int gm = cta >> 5;
    const int gn = cta & 31;
    const int b0 = gm * MB;
    const int n0 = gn * NB;
    const float inv_tau = 1.0f / (*taup);

    const int nh = wid & 1;
    const int kw = wid >> 1;
    const int kc = kw * 128;
    const int lq = lane >> 2;
    const int lr = lane & 3;

    const unsigned base = *(volatile unsigned *)&g_flags[gm][gn][0];

    // ---- One-time: W slice fragments -> registers (fp16 split pair) ----
    uint32_t Wr1[8][2][2], Wr2[8][2][2];
    #pragma unroll
    for (int ks = 0; ks < 8; ++ks) {
        #pragma unroll
        for (int nt = 0; nt < 2; ++nt) {
            const float *wrow = W_rec + (size_t)(n0 + nh * 16 + nt * 8 + lq) * HH
                                + kc + ks * 16 + 2 * lr;
            split2h(wrow[0], wrow[1], Wr1[ks][nt][0], Wr2[ks][nt][0]);
            split2h(wrow[8], wrow[9], Wr1[ks][nt][1], Wr2[ks][nt][1]);
        }
    }

    // ---- One-time: zero fp32 h slice (smem) and fp16 buf0 (gmem) ----
    float *hs = (float *)(smem + OFF_HS);
    const int ob = tid >> 5, on = tid & 31;
    hs[tid] = 0.0f;
    g_h16[0][b0 + ob][n0 + on] = __float2half(0.0f);

    __syncthreads();
    if (tid == 0) { __threadfence(); atomicExch(&g_flags[gm][gn][0], base + 1u); }

    float *zr = (float *)(smem + OFF_ZR);
    const uint32_t ab1 = sb + OFF_H +
        (uint32_t)((lane & 15) * PITCH_H + (lane >> 4) * 16 + kc * 2);

    const int bg = b0 + ob, ng = n0 + on;
    size_t oidx = (size_t)bg * TT * HH + ng;
    volatile unsigned *myflag_row = &g_flags[gm][0][0];

    float u_cur = __ldcg(out + oidx);

    for (int t = 0; t < TT; ++t) {
        const int rb = t & 1;
        const int nb = rb ^ 1;

        // ---- Wait: 32 group flags (warp0, one per lane; bounded) ----
        if (wid == 0) {
            const unsigned target = base + (unsigned)t + 1u;
            volatile unsigned *fp = myflag_row + lane * 32;
            unsigned c = 0;
            while ((int)(*fp - target) < 0) {
                if (++c > (1u << 26)) break;
                if (c > 4096u) __nanosleep(64);
            }
            __threadfence();
        }
        __syncthreads();

        // ---- Stage h slice [16 b][1024 k] fp16: group A (k<512), B (k>=512) ----
        const __half *hb = &g_h16[rb][0][0];
        #pragma unroll
        for (int i = 0; i < 2; ++i) {
            int id = i * NTHR + tid;            // 0..1023
            int row = id >> 6;                  // 0..15
            int c16 = id & 63;
            const void *src = hb + (b0 + row) * HH + c16 * 8;
            uint32_t dst = sb + OFF_H + row * PITCH_H + c16 * 16;
            CP_ASYNC16(dst, src);
        }
        CP_COMMIT();
        #pragma unroll
        for (int i = 0; i < 2; ++i) {
            int id = i * NTHR + tid;
            int row = id >> 6;
            int c16 = (id & 63) + 64;
            const void *src = hb + (b0 + row) * HH + c16 * 8;
            uint32_t dst = sb + OFF_H + row * PITCH_H + c16 * 16;
            CP_ASYNC16(dst, src);
        }
        CP_COMMIT();

        float u_next = 0.0f;
        if (t < TT - 1) u_next = __ldcg(out + oidx + HH);

        float D[2][4];
        #pragma unroll
        for (int nt = 0; nt < 2; ++nt)
            #pragma unroll
            for (int j = 0; j < 4; ++j) D[nt][j] = 0.0f;

        CP_WAIT(1);
        __syncthreads();

        // ---- Phase 1: warps with k<512 (covered by group A) ----
        if (wid < 8) {
            #pragma unroll
            for (int ks = 0; ks < 8; ++ks) {
                uint32_t a[4];
                ldsm_x4(a, ab1 + ks * 32);
                #pragma unroll
                for (int nt = 0; nt < 2; ++nt) {
                    mma16816h(D[nt], a, Wr1[ks][nt]);
                    mma16816h(D[nt], a, Wr2[ks][nt]);
                }
            }
        }

        CP_WAIT(0);
        __syncthreads();

        // ---- Phase 2: warps with k>=512 ----
        if (wid >= 8) {
            #pragma unroll
            for (int ks = 0; ks < 8; ++ks) {
                uint32_t a[4];
                ldsm_x4(a, ab1 + ks * 32);
                #pragma unroll
                for (int nt = 0; nt < 2; ++nt) {
                    mma16816h(D[nt], a, Wr1[ks][nt]);
                    mma16816h(D[nt], a, Wr2[ks][nt]);
                }
            }
        }

        // ---- k-split partials -> smem zred[8][16][ZP] ----
        {
            int zb = kw * (16 * ZP) + lq * ZP + nh * 16 + 2 * lr;
            #pragma unroll
            for (int nt = 0; nt < 2; ++nt) {
                zr[zb + nt * 8]     = D[nt][0];
                zr[zb + nt * 8 + 1] = D[nt][1];
                zr[zb + 8 * ZP + nt * 8]     = D[nt][2];
                zr[zb + 8 * ZP + nt * 8 + 1] = D[nt][3];
            }
        }
        __syncthreads();

        // ---- Epilogue; publish BEFORE out-store ----
        float s = 0.0f;
        #pragma unroll
        for (int q = 0; q < 8; ++q) s += zr[q * (16 * ZP) + ob * ZP + on];
        float hp = hs[tid];
        float f = tanhf(u_cur + s);
        float hn = hp + (f - hp) * inv_tau;
        g_h16[nb][bg][ng] = __float2half(hn);
        __syncthreads();
        if (t < TT - 1 && tid == 0) {
            __threadfence();
            atomicExch(&g_flags[gm][gn][0], base + (unsigned)t + 2u);
        }

        // off-critical-path stores
        out[oidx] = hn;
        hs[tid] = hn;
        if (t == TT - 1)
            out[(size_t)BB * TT * HH + (size_t)bg * HH + ng] = hn;

        u_cur = u_next;
        oidx += HH;
    }
}

// =====================================================================
// Projection (HMMA) — R13-proven version (~92us), unchanged.
// =====================================================================
__global__ void __launch_bounds__(256, 2)
proj_mma(const float *__restrict__ seq, const float *__restrict__ W_in,
         const float *__restrict__ b_in, const float *__restrict__ bias,
         float *__restrict__ out) {
    extern __shared__ char sm[];
    const uint32_t sb = (uint32_t)__cvta_generic_to_shared(sm);
    const int tid = threadIdx.x;
    const int wid = tid >> 5;
    const int lane = tid & 31;
    const int bt0 = blockIdx.x * P2M;
    const int h0 = blockIdx.y * P2N;
    const int wm = wid & 3;
    const int wn = wid >> 2;

    #pragma unroll
    for (int i = 0; i < 16; ++i) {
        int id = tid + i * 256;
        int row = id >> 5;
        int c4 = id & 31;
        float4 v = *(const float4 *)(seq + (size_t)(bt0 + row) * DD + c4 * 4);
        uint32_t p0, r0, p1, r1;
        split2(v.x, v.y, p0, r0);
        split2(v.z, v.w, p1, r1);
        *(uint2 *)(sm + POF_A1 + row * PA + c4 * 8) = make_uint2(p0, p1);
        *(uint2 *)(sm + POF_A2 + row * PA + c4 * 8) = make_uint2(r0, r1);
    }
    #pragma unroll
    for (int i = 0; i < 8; ++i) {
        int id = tid + i * 256;
        int row = id >> 5;
        int c4 = id & 31;
        float4 v = *(const float4 *)(W_in + (size_t)(h0 + row) * DD + c4 * 4);
        uint32_t p0, r0, p1, r1;
        split2(v.x, v.y, p0, r0);
        split2(v.z, v.w, p1, r1);
        *(uint2 *)(sm + POF_W1 + row * PA + c4 * 8) = make_uint2(p0, p1);
        *(uint2 *)(sm + POF_W2 + row * PA + c4 * 8) = make_uint2(r0, r1);
    }
    __syncthreads();

    const uint32_t aA = sb + POF_A1 +
        (uint32_t)((wm * 32 + (lane & 15)) * PA + (lane >> 4) * 16);
    const uint32_t aW = sb + POF_W1 +
        (uint32_t)((wn * 32 + ((lane >> 4) & 1) * 8 + (lane & 7)) * PA
                   + ((lane >> 3) & 1) * 16);

    float D[2][4][4];
    #pragma unroll
    for (int mt = 0; mt < 2; ++mt)
        #pragma unroll
        for (int nt = 0; nt < 4; ++nt)
            #pragma unroll
            for (int j = 0; j < 4; ++j) D[mt][nt][j] = 0.0f;

    #pragma unroll
    for (int ks = 0; ks < 8; ++ks) {
        uint32_t a1[2][4], a2[2][4];
        ldsm_x4(a1[0], aA + ks * 32);
        ldsm_x4(a1[1], aA + 16 * PA + ks * 32);
        ldsm_x4(a2[0], aA + (POF_A2 - POF_A1) + ks * 32);
        ldsm_x4(a2[1], aA + (POF_A2 - POF_A1) + 16 * PA + ks * 32);
        uint32_t b1[8], b2[8];
        ldsm_x4(b1,     aW + ks * 32);
        ldsm_x4(b1 + 4, aW + 16 * PA + ks * 32);
        ldsm_x4(b2,     aW + (POF_W2 - POF_W1) + ks * 32);
        ldsm_x4(b2 + 4, aW + (POF_W2 - POF_W1) + 16 * PA + ks * 32);
        #pragma unroll
        for (int mt = 0; mt < 2; ++mt)
            #pragma unroll
            for (int nt = 0; nt < 4; ++nt) {
                mma16816(D[mt][nt], a1[mt], &b1[nt * 2]);
                mma16816(D[mt][nt], a1[mt], &b2[nt * 2]);
                mma16816(D[mt][nt], a2[mt], &b1[nt * 2]);
            }
    }

    #pragma unroll
    for (int nt = 0; nt < 4; ++nt) {
        int col = h0 + wn * 32 + nt * 8 + 2 * (lane & 3);
        float2 bi = *(const float2 *)(b_in + col);
        float2 bs = *(const float2 *)(bias + col);
        float bb0 = bi.x + bs.x, bb1 = bi.y + bs.y;
        #pragma unroll
        for (int mt = 0; mt < 2; ++mt) {
            int row0 = bt0 + wm * 32 + mt * 16 + (lane >> 2);
            *(float2 *)(out + (size_t)row0 * HH + col) =
                make_float2(D[mt][nt][0] + bb0, D[mt][nt][1] + bb1);
            *(float2 *)(out + (size_t)(row0 + 8) * HH + col) =
                make_float2(D[mt][nt][2] + bb0, D[mt][nt][3] + bb1);
        }
    }
}

extern "C" void kernel_launch(void *const *d_in, const int *in_sizes, int n_in,
                              void *d_out, int out_size) {
    const float *seq = (const float *)d_in[0];
    const float *W_in = (const float *)d_in[1];
    const float *b_in = (const float *)d_in[2];
    const float *W_rec = (const float *)d_in[3];
    const float *bias = (const float *)d_in[4];
    const float *tau = (const float *)d_in[5];
    float *out = (float *)d_out;

    cudaFuncSetAttribute(proj_mma, cudaFuncAttributeMaxDynamicSharedMemorySize,
                         PROJ_SMEM);
    cudaFuncSetAttribute(scan_mma, cudaFuncAttributeMaxDynamicSharedMemorySize,
                         SMEM_TOTAL);

    proj_mma<<<dim3(BT / P2M, HH / P2N), 256, PROJ_SMEM>>>(
        seq, W_in, b_in, bias, out);
    scan_mma<<<GRID, NTHR, SMEM_TOTAL>>>(W_rec, tau, out);
}